// round 1
// baseline (speedup 1.0000x reference)
#include <cuda_runtime.h>
#include <math.h>

#define S_   1024
#define DM_  1024
#define B_   8
#define H_   16
#define D_   64

// Scratch (allocation-free rule: __device__ globals)
__device__ float g_Qh[B_*H_*S_*D_];   // [b,h,s,d]
__device__ float g_Kh[B_*H_*S_*D_];
__device__ float g_Vh[B_*H_*S_*D_];
__device__ float g_X [B_*S_*DM_];     // [b,s,h*64+d]

// ---------------------------------------------------------------------------
// Projection GEMM: C[b,h,s,d] = sum_m A[b,s,m]*W[h,m,d] + bias[h*64+d]
// M = B*S = 8192 (rows m = b*1024+s), N = H*D = 1024 (cols n = h*64+d), K=1024
// BM=BN=128, BK=8, 256 threads, 8x8 per-thread tile.
// ---------------------------------------------------------------------------
__global__ __launch_bounds__(256) void proj_gemm(
    const float* __restrict__ A, const float* __restrict__ W,
    const float* __restrict__ bias, float* __restrict__ C)
{
    __shared__ float As[8][132];
    __shared__ float Bs[8][132];
    const int m0 = blockIdx.y * 128;
    const int n0 = blockIdx.x * 128;
    const int tid = threadIdx.x;
    const int tx = tid & 15, ty = tid >> 4;

    float acc[8][8] = {};

    const int ar = tid >> 1;          // A row in tile 0..127
    const int ac = (tid & 1) * 4;     // A col 0 or 4
    const int br = tid >> 5;          // B k-row 0..7
    const int bc = (tid & 31) * 4;    // B n-col (4 consecutive n, never crosses h)

    const int nb = n0 + bc;
    const int hb = nb >> 6, db = nb & 63;

    for (int k0 = 0; k0 < 1024; k0 += 8) {
        float4 av = *(const float4*)(A + (size_t)(m0 + ar) * 1024 + k0 + ac);
        float4 bv = *(const float4*)(W + ((size_t)hb * 1024 + (k0 + br)) * 64 + db);
        __syncthreads();
        As[ac+0][ar] = av.x; As[ac+1][ar] = av.y;
        As[ac+2][ar] = av.z; As[ac+3][ar] = av.w;
        *(float4*)&Bs[br][bc] = bv;
        __syncthreads();
        #pragma unroll
        for (int kk = 0; kk < 8; kk++) {
            float ra[8], rb[8];
            #pragma unroll
            for (int i = 0; i < 8; i++) ra[i] = As[kk][ty*8+i];
            #pragma unroll
            for (int j = 0; j < 8; j++) rb[j] = Bs[kk][tx*8+j];
            #pragma unroll
            for (int i = 0; i < 8; i++)
                #pragma unroll
                for (int j = 0; j < 8; j++)
                    acc[i][j] = fmaf(ra[i], rb[j], acc[i][j]);
        }
    }
    #pragma unroll
    for (int i = 0; i < 8; i++) {
        int m = m0 + ty*8 + i;
        int b = m >> 10, s = m & 1023;
        #pragma unroll
        for (int j = 0; j < 8; j++) {
            int n = n0 + tx*8 + j;
            int h = n >> 6, d = n & 63;
            C[(((size_t)(b*H_ + h))*S_ + s)*D_ + d] = acc[i][j] + bias[n];
        }
    }
}

// ---------------------------------------------------------------------------
// Output GEMM: C[m,n] = sum_k A[m,k]*Wo[k,n] + bo[n]   (all row-major)
// ---------------------------------------------------------------------------
__global__ __launch_bounds__(256) void out_gemm(
    const float* __restrict__ A, const float* __restrict__ Wo,
    const float* __restrict__ bo, float* __restrict__ C)
{
    __shared__ float As[8][132];
    __shared__ float Bs[8][132];
    const int m0 = blockIdx.y * 128;
    const int n0 = blockIdx.x * 128;
    const int tid = threadIdx.x;
    const int tx = tid & 15, ty = tid >> 4;

    float acc[8][8] = {};

    const int ar = tid >> 1;
    const int ac = (tid & 1) * 4;
    const int br = tid >> 5;
    const int bc = (tid & 31) * 4;

    for (int k0 = 0; k0 < 1024; k0 += 8) {
        float4 av = *(const float4*)(A + (size_t)(m0 + ar) * 1024 + k0 + ac);
        float4 bv = *(const float4*)(Wo + (size_t)(k0 + br) * 1024 + n0 + bc);
        __syncthreads();
        As[ac+0][ar] = av.x; As[ac+1][ar] = av.y;
        As[ac+2][ar] = av.z; As[ac+3][ar] = av.w;
        *(float4*)&Bs[br][bc] = bv;
        __syncthreads();
        #pragma unroll
        for (int kk = 0; kk < 8; kk++) {
            float ra[8], rb[8];
            #pragma unroll
            for (int i = 0; i < 8; i++) ra[i] = As[kk][ty*8+i];
            #pragma unroll
            for (int j = 0; j < 8; j++) rb[j] = Bs[kk][tx*8+j];
            #pragma unroll
            for (int i = 0; i < 8; i++)
                #pragma unroll
                for (int j = 0; j < 8; j++)
                    acc[i][j] = fmaf(ra[i], rb[j], acc[i][j]);
        }
    }
    #pragma unroll
    for (int i = 0; i < 8; i++) {
        int m = m0 + ty*8 + i;
        #pragma unroll
        for (int j = 0; j < 8; j++) {
            int n = n0 + tx*8 + j;
            C[(size_t)m * 1024 + n] = acc[i][j] + bo[n];
        }
    }
}

// ---------------------------------------------------------------------------
// Flash attention (fp32, exact reference mask semantics).
// grid: (S/64, B*H). 256 threads (16x16), 4x4 per-thread fragments.
// Mask: masked = (t > s) || (t >= S - pad[b]) || (pad[b]==0); score = raw/32 - 1e9*masked
// (fp32 absorption makes all-masked rows exactly uniform, matching the reference quirk)
// ---------------------------------------------------------------------------
#define ATTN_SMEM (4 * 64 * 65 * 4)

__global__ __launch_bounds__(256) void attn_kernel(
    const int* __restrict__ pad, float* __restrict__ X)
{
    extern __shared__ float sm[];
    float (*Qs)[65] = (float(*)[65])(sm);
    float (*Ks)[65] = (float(*)[65])(sm + 64*65);
    float (*Vs)[65] = (float(*)[65])(sm + 2*64*65);
    float (*Ps)[65] = (float(*)[65])(sm + 3*64*65);

    const int qt = blockIdx.x;
    const int bh = blockIdx.y;
    const int b  = bh >> 4;
    const int h  = bh & 15;
    const int padb = pad[b];
    const int tid = threadIdx.x;
    const int tx = tid & 15, ty = tid >> 4;
    const int q0 = qt * 64;

    const float* Qp = g_Qh + (size_t)bh * S_ * D_;
    const float* Kp = g_Kh + (size_t)bh * S_ * D_;
    const float* Vp = g_Vh + (size_t)bh * S_ * D_;

    // Load Q tile (64x64)
    #pragma unroll
    for (int u = 0; u < 4; u++) {
        int li = tid + u * 256;          // 0..1023 float4 slots
        int r = li >> 4, c4 = (li & 15) * 4;
        float4 v = *(const float4*)(Qp + (size_t)(q0 + r) * 64 + c4);
        Qs[r][c4+0] = v.x; Qs[r][c4+1] = v.y; Qs[r][c4+2] = v.z; Qs[r][c4+3] = v.w;
    }

    float acc[4][4] = {};
    float mrow[4], lrow[4];
    #pragma unroll
    for (int i = 0; i < 4; i++) { mrow[i] = -INFINITY; lrow[i] = 0.f; }

    const int qmax = q0 + 63;
    for (int jt = 0; jt < 16; jt++) {
        const int t0 = jt * 64;
        // Exact skip: valid only when pad != 0 (masked lanes underflow to 0)
        if (padb != 0 && (t0 > qmax || t0 >= S_ - padb)) continue;

        __syncthreads();
        #pragma unroll
        for (int u = 0; u < 4; u++) {
            int li = tid + u * 256;
            int r = li >> 4, c4 = (li & 15) * 4;
            float4 kv = *(const float4*)(Kp + (size_t)(t0 + r) * 64 + c4);
            Ks[r][c4+0] = kv.x; Ks[r][c4+1] = kv.y; Ks[r][c4+2] = kv.z; Ks[r][c4+3] = kv.w;
            float4 vv = *(const float4*)(Vp + (size_t)(t0 + r) * 64 + c4);
            Vs[r][c4+0] = vv.x; Vs[r][c4+1] = vv.y; Vs[r][c4+2] = vv.z; Vs[r][c4+3] = vv.w;
        }
        __syncthreads();

        // S = Q @ K^T (4x4 fragment)
        float sc[4][4] = {};
        #pragma unroll
        for (int k = 0; k < 64; k++) {
            float rq[4], rk[4];
            #pragma unroll
            for (int i = 0; i < 4; i++) rq[i] = Qs[ty*4+i][k];
            #pragma unroll
            for (int j = 0; j < 4; j++) rk[j] = Ks[tx*4+j][k];
            #pragma unroll
            for (int i = 0; i < 4; i++)
                #pragma unroll
                for (int j = 0; j < 4; j++)
                    sc[i][j] = fmaf(rq[i], rk[j], sc[i][j]);
        }

        // scale + mask (reference semantics, fp32 absorption preserved)
        #pragma unroll
        for (int i = 0; i < 4; i++) {
            const int srow = q0 + ty*4 + i;
            #pragma unroll
            for (int j = 0; j < 4; j++) {
                const int t = t0 + tx*4 + j;
                float v = sc[i][j] * 0.03125f;
                bool masked = (t > srow) || (t >= S_ - padb) || (padb == 0);
                sc[i][j] = masked ? (v - 1e9f) : v;
            }
        }

        // online softmax per row (16-lane shuffle reduce)
        #pragma unroll
        for (int i = 0; i < 4; i++) {
            float tm = sc[i][0];
            #pragma unroll
            for (int j = 1; j < 4; j++) tm = fmaxf(tm, sc[i][j]);
            #pragma unroll
            for (int o = 8; o > 0; o >>= 1)
                tm = fmaxf(tm, __shfl_xor_sync(0xffffffffu, tm, o, 16));
            const float mnew  = fmaxf(mrow[i], tm);
            const float alpha = __expf(mrow[i] - mnew);
            float rs = 0.f;
            #pragma unroll
            for (int j = 0; j < 4; j++) {
                float p = __expf(sc[i][j] - mnew);
                sc[i][j] = p;
                rs += p;
            }
            #pragma unroll
            for (int o = 8; o > 0; o >>= 1)
                rs += __shfl_xor_sync(0xffffffffu, rs, o, 16);
            lrow[i] = lrow[i] * alpha + rs;
            mrow[i] = mnew;
            #pragma unroll
            for (int j = 0; j < 4; j++) acc[i][j] *= alpha;
            #pragma unroll
            for (int j = 0; j < 4; j++) Ps[ty*4+i][tx*4+j] = sc[i][j];
        }
        __syncthreads();

        // acc += P @ V
        #pragma unroll
        for (int k = 0; k < 64; k++) {
            float rp[4], rv[4];
            #pragma unroll
            for (int i = 0; i < 4; i++) rp[i] = Ps[ty*4+i][k];
            #pragma unroll
            for (int j = 0; j < 4; j++) rv[j] = Vs[k][tx*4+j];
            #pragma unroll
            for (int i = 0; i < 4; i++)
                #pragma unroll
                for (int j = 0; j < 4; j++)
                    acc[i][j] = fmaf(rp[i], rv[j], acc[i][j]);
        }
    }

    // write to X[b,s, h*64+d]
    #pragma unroll
    for (int i = 0; i < 4; i++) {
        const int srow = q0 + ty*4 + i;
        const float inv = 1.f / lrow[i];
        #pragma unroll
        for (int j = 0; j < 4; j++) {
            const int d = tx*4 + j;
            X[((size_t)(b*S_ + srow)) * DM_ + h*64 + d] = acc[i][j] * inv;
        }
    }
}

// ---------------------------------------------------------------------------
extern "C" void kernel_launch(void* const* d_in, const int* in_sizes, int n_in,
                              void* d_out, int out_size)
{
    const float* Q   = (const float*)d_in[0];
    const float* K   = (const float*)d_in[1];
    const float* V   = (const float*)d_in[2];
    const int*   pad = (const int*)  d_in[3];
    const float* Wq  = (const float*)d_in[4];
    const float* bq  = (const float*)d_in[5];
    const float* Wk  = (const float*)d_in[6];
    const float* bk  = (const float*)d_in[7];
    const float* Wv  = (const float*)d_in[8];
    const float* bv  = (const float*)d_in[9];
    const float* Wo  = (const float*)d_in[10];
    const float* bo  = (const float*)d_in[11];
    float* out = (float*)d_out;

    float *qh, *kh, *vh, *xc;
    cudaGetSymbolAddress((void**)&qh, g_Qh);
    cudaGetSymbolAddress((void**)&kh, g_Kh);
    cudaGetSymbolAddress((void**)&vh, g_Vh);
    cudaGetSymbolAddress((void**)&xc, g_X);

    cudaFuncSetAttribute(attn_kernel,
                         cudaFuncAttributeMaxDynamicSharedMemorySize, ATTN_SMEM);

    dim3 gproj(8, 64);   // N tiles x M tiles
    proj_gemm<<<gproj, 256>>>(Q, Wq, bq, qh);
    proj_gemm<<<gproj, 256>>>(K, Wk, bk, kh);
    proj_gemm<<<gproj, 256>>>(V, Wv, bv, vh);

    attn_kernel<<<dim3(16, 128), 256, ATTN_SMEM>>>(pad, xc);

    out_gemm<<<gproj, 256>>>(xc, Wo, bo, out);
}

// round 3
// speedup vs baseline: 1.9526x; 1.9526x over previous
#include <cuda_runtime.h>
#include <cuda_bf16.h>
#include <mma.h>
#include <math.h>
#include <stdint.h>

using namespace nvcuda;

#define S_   1024
#define DM_  1024
#define B_   8
#define H_   16
#define D_   64

// ---------------- scratch (__device__ globals; no allocation) ----------------
__device__ float g_Qh[B_*H_*S_*D_];   // [b,h,s,d] fp32
__device__ float g_Kh[B_*H_*S_*D_];
__device__ float g_Vh[B_*H_*S_*D_];
__device__ __nv_bfloat16 g_Ahi[B_*S_*DM_];  // activation hi/lo (Q/K/V input, then X)
__device__ __nv_bfloat16 g_Alo[B_*S_*DM_];
__device__ __nv_bfloat16 g_Whi[DM_*DM_];    // weight-transposed hi/lo [N][K]
__device__ __nv_bfloat16 g_Wlo[DM_*DM_];

// ---------------- helpers ----------------
__device__ __forceinline__ uint32_t smem_u32(const void* p) {
    uint32_t a;
    asm("{ .reg .u64 t; cvta.to.shared.u64 t, %1; cvt.u32.u64 %0, t; }"
        : "=r"(a) : "l"(p));
    return a;
}
__device__ __forceinline__ void cp16(uint32_t dst, const void* src) {
    asm volatile("cp.async.cg.shared.global [%0], [%1], 16;" :: "r"(dst), "l"(src));
}
__device__ __forceinline__ uint32_t pack2(float a, float b, float* ra, float* rb) {
    __nv_bfloat16 ha = __float2bfloat16(a), hb = __float2bfloat16(b);
    *ra = a - __bfloat162float(ha);
    *rb = b - __bfloat162float(hb);
    return (uint32_t)__bfloat16_as_ushort(ha) |
           ((uint32_t)__bfloat16_as_ushort(hb) << 16);
}
__device__ __forceinline__ uint32_t pack2lo(float a, float b) {
    __nv_bfloat16 ha = __float2bfloat16(a), hb = __float2bfloat16(b);
    return (uint32_t)__bfloat16_as_ushort(ha) |
           ((uint32_t)__bfloat16_as_ushort(hb) << 16);
}

// ---------------- conversion kernels ----------------
__global__ __launch_bounds__(256) void split_act(
    const float4* __restrict__ src, uint2* __restrict__ hi, uint2* __restrict__ lo, int n4)
{
    int i = blockIdx.x * 256 + threadIdx.x;
    if (i >= n4) return;
    float4 v = src[i];
    float rx, ry, rz, rw;
    uint2 h, l;
    h.x = pack2(v.x, v.y, &rx, &ry);
    h.y = pack2(v.z, v.w, &rz, &rw);
    l.x = pack2lo(rx, ry);
    l.y = pack2lo(rz, rw);
    hi[i] = h; lo[i] = l;
}

// weight transpose+split: out[n][k]; mode0 src=W[h][k][d] (n=h*64+d), mode1 src=Wo[k][n]
__global__ __launch_bounds__(256) void split_wT(
    const float* __restrict__ W, __nv_bfloat16* __restrict__ hi,
    __nv_bfloat16* __restrict__ lo, int mode)
{
    __shared__ float t[32][33];
    int k0 = blockIdx.x * 32, n0 = blockIdx.y * 32;
    int tx = threadIdx.x, ty = threadIdx.y;   // 32 x 8
    #pragma unroll
    for (int i = 0; i < 4; i++) {
        int k = k0 + ty + 8*i, n = n0 + tx;
        float v = mode ? W[(size_t)k * 1024 + n]
                       : W[(((size_t)(n >> 6)) * 1024 + k) * 64 + (n & 63)];
        t[ty + 8*i][tx] = v;
    }
    __syncthreads();
    #pragma unroll
    for (int i = 0; i < 4; i++) {
        int n = n0 + ty + 8*i, k = k0 + tx;
        float v = t[tx][ty + 8*i];
        __nv_bfloat16 h = __float2bfloat16(v);
        __nv_bfloat16 l = __float2bfloat16(v - __bfloat162float(h));
        hi[(size_t)n * 1024 + k] = h;
        lo[(size_t)n * 1024 + k] = l;
    }
}

// ---------------- wmma GEMM (bf16x3 emulated fp32) ----------------
// C[8192 x 1024] = A[8192 x 1024] * B^T (B stored [N][K]) + bias[n]
// CTA tile 128x128, K chunks of 32 (2x k16), 8 warps (2M x 4N), warp tile 64x32.
// SMEM per stage: 4 matrices (Ahi,Alo,Bhi,Blo), each [128][40] bf16 (pad 32->40).
#define LDSM   40
#define MATB   (128 * LDSM * 2)        // 10240 bytes per matrix
#define STAGEB (4 * MATB)              // 40960 bytes per stage
#define GSMEM  (2 * STAGEB + 16 * 128 * 4)   // + bias tile 8KB

typedef wmma::fragment<wmma::matrix_a, 16,16,16, __nv_bfloat16, wmma::row_major> FragA;
typedef wmma::fragment<wmma::matrix_b, 16,16,16, __nv_bfloat16, wmma::col_major> FragB;
typedef wmma::fragment<wmma::accumulator, 16,16,16, float> FragC;

__device__ __forceinline__ void issue_stage(
    const __nv_bfloat16* __restrict__ Ahi, const __nv_bfloat16* __restrict__ Alo,
    const __nv_bfloat16* __restrict__ Bhi, const __nv_bfloat16* __restrict__ Blo,
    uint32_t sbase, int stage, int m0, int n0, int k0, int tid)
{
    #pragma unroll
    for (int u = 0; u < 8; u++) {
        int chunk = u * 256 + tid;         // 2048 chunks of 16B
        int mat = chunk >> 9;              // 512 chunks per matrix
        int r   = (chunk >> 2) & 127;
        int c   = chunk & 3;               // 16B chunk within row (8 bf16)
        const __nv_bfloat16* g;
        if      (mat == 0) g = Ahi + (size_t)(m0 + r) * 1024 + k0 + c * 8;
        else if (mat == 1) g = Alo + (size_t)(m0 + r) * 1024 + k0 + c * 8;
        else if (mat == 2) g = Bhi + (size_t)(n0 + r) * 1024 + k0 + c * 8;
        else               g = Blo + (size_t)(n0 + r) * 1024 + k0 + c * 8;
        uint32_t dst = sbase + (uint32_t)(stage * STAGEB + mat * MATB + r * (LDSM*2) + c * 16);
        cp16(dst, g);
    }
    asm volatile("cp.async.commit_group;" ::: "memory");
}

__global__ __launch_bounds__(256) void mma_gemm(
    const __nv_bfloat16* __restrict__ Ahi, const __nv_bfloat16* __restrict__ Alo,
    const __nv_bfloat16* __restrict__ Bhi, const __nv_bfloat16* __restrict__ Blo,
    const float* __restrict__ bias, float* __restrict__ out, int mode)
{
    extern __shared__ char sm[];
    float* sBias = (float*)(sm + 2 * STAGEB);
    const uint32_t sbase = smem_u32(sm);
    const int tid = threadIdx.x;
    const int wid = tid >> 5;
    const int m0 = blockIdx.y * 128;
    const int n0 = blockIdx.x * 128;
    const int wm = wid >> 2;     // 0..1
    const int wn = wid & 3;      // 0..3

    // bias tile: 16 identical rows of bias[n0..n0+127]
    for (int idx = tid; idx < 16 * 128; idx += 256)
        sBias[idx] = bias[n0 + (idx & 127)];
    __syncthreads();

    FragC acc[4][2];
    #pragma unroll
    for (int i = 0; i < 4; i++)
        #pragma unroll
        for (int j = 0; j < 2; j++)
            wmma::load_matrix_sync(acc[i][j], sBias + wn*32 + j*16, 128, wmma::mem_row_major);

    issue_stage(Ahi, Alo, Bhi, Blo, sbase, 0, m0, n0, 0, tid);

    for (int kc = 0; kc < 32; kc++) {
        const int s = kc & 1;
        if (kc + 1 < 32) {
            issue_stage(Ahi, Alo, Bhi, Blo, sbase, s ^ 1, m0, n0, (kc + 1) * 32, tid);
            asm volatile("cp.async.wait_group 1;" ::: "memory");
        } else {
            asm volatile("cp.async.wait_group 0;" ::: "memory");
        }
        __syncthreads();

        const __nv_bfloat16* stg = (const __nv_bfloat16*)(sm + s * STAGEB);
        const __nv_bfloat16* sAh = stg;
        const __nv_bfloat16* sAl = stg + 128 * LDSM;
        const __nv_bfloat16* sBh = stg + 2 * 128 * LDSM;
        const __nv_bfloat16* sBl = stg + 3 * 128 * LDSM;

        #pragma unroll
        for (int ks = 0; ks < 2; ks++) {
            FragA ah[4], al[4];
            FragB bh[2], bl[2];
            #pragma unroll
            for (int i = 0; i < 4; i++) {
                wmma::load_matrix_sync(ah[i], sAh + (wm*64 + i*16) * LDSM + ks*16, LDSM);
                wmma::load_matrix_sync(al[i], sAl + (wm*64 + i*16) * LDSM + ks*16, LDSM);
            }
            #pragma unroll
            for (int j = 0; j < 2; j++) {
                wmma::load_matrix_sync(bh[j], sBh + (wn*32 + j*16) * LDSM + ks*16, LDSM);
                wmma::load_matrix_sync(bl[j], sBl + (wn*32 + j*16) * LDSM + ks*16, LDSM);
            }
            #pragma unroll
            for (int i = 0; i < 4; i++)
                #pragma unroll
                for (int j = 0; j < 2; j++) {
                    wmma::mma_sync(acc[i][j], ah[i], bh[j], acc[i][j]);
                    wmma::mma_sync(acc[i][j], ah[i], bl[j], acc[i][j]);
                    wmma::mma_sync(acc[i][j], al[i], bh[j], acc[i][j]);
                }
        }
        __syncthreads();
    }

    // epilogue: store directly to global (per-16x16-tile strided store)
    #pragma unroll
    for (int i = 0; i < 4; i++) {
        const int m = m0 + wm*64 + i*16;
        #pragma unroll
        for (int j = 0; j < 2; j++) {
            const int n = n0 + wn*32 + j*16;
            if (mode == 0) {
                const int b = m >> 10, srow = m & 1023;
                const int h = n >> 6,  d = n & 63;
                float* p = out + (((size_t)(b*16 + h)) * 1024 + srow) * 64 + d;
                wmma::store_matrix_sync(p, acc[i][j], 64, wmma::mem_row_major);
            } else {
                float* p = out + (size_t)m * 1024 + n;
                wmma::store_matrix_sync(p, acc[i][j], 1024, wmma::mem_row_major);
            }
        }
    }
}

// ---------------- flash attention (fp32, exact reference mask) ----------------
#define ATTN_SMEM (4 * 64 * 65 * 4)

__global__ __launch_bounds__(256) void attn_kernel(
    const int* __restrict__ pad,
    __nv_bfloat16* __restrict__ Xhi, __nv_bfloat16* __restrict__ Xlo)
{
    extern __shared__ float smf[];
    float (*Qs)[65] = (float(*)[65])(smf);
    float (*Ks)[65] = (float(*)[65])(smf + 64*65);
    float (*Vs)[65] = (float(*)[65])(smf + 2*64*65);
    float (*Ps)[65] = (float(*)[65])(smf + 3*64*65);

    const int qt = blockIdx.x;
    const int bh = blockIdx.y;
    const int b  = bh >> 4;
    const int h  = bh & 15;
    const int padb = pad[b];
    const int tid = threadIdx.x;
    const int tx = tid & 15, ty = tid >> 4;
    const int q0 = qt * 64;

    const float* Qp = g_Qh + (size_t)bh * S_ * D_;
    const float* Kp = g_Kh + (size_t)bh * S_ * D_;
    const float* Vp = g_Vh + (size_t)bh * S_ * D_;

    #pragma unroll
    for (int u = 0; u < 4; u++) {
        int li = tid + u * 256;
        int r = li >> 4, c4 = (li & 15) * 4;
        float4 v = *(const float4*)(Qp + (size_t)(q0 + r) * 64 + c4);
        Qs[r][c4+0] = v.x; Qs[r][c4+1] = v.y; Qs[r][c4+2] = v.z; Qs[r][c4+3] = v.w;
    }

    float acc[4][4] = {};
    float mrow[4], lrow[4];
    #pragma unroll
    for (int i = 0; i < 4; i++) { mrow[i] = -INFINITY; lrow[i] = 0.f; }

    const int qmax = q0 + 63;
    for (int jt = 0; jt < 16; jt++) {
        const int t0 = jt * 64;
        if (padb != 0 && (t0 > qmax || t0 >= S_ - padb)) continue;

        __syncthreads();
        #pragma unroll
        for (int u = 0; u < 4; u++) {
            int li = tid + u * 256;
            int r = li >> 4, c4 = (li & 15) * 4;
            float4 kv = *(const float4*)(Kp + (size_t)(t0 + r) * 64 + c4);
            Ks[r][c4+0] = kv.x; Ks[r][c4+1] = kv.y; Ks[r][c4+2] = kv.z; Ks[r][c4+3] = kv.w;
            float4 vv = *(const float4*)(Vp + (size_t)(t0 + r) * 64 + c4);
            Vs[r][c4+0] = vv.x; Vs[r][c4+1] = vv.y; Vs[r][c4+2] = vv.z; Vs[r][c4+3] = vv.w;
        }
        __syncthreads();

        float sc[4][4] = {};
        #pragma unroll
        for (int k = 0; k < 64; k++) {
            float rq[4], rk[4];
            #pragma unroll
            for (int i = 0; i < 4; i++) rq[i] = Qs[ty*4+i][k];
            #pragma unroll
            for (int j = 0; j < 4; j++) rk[j] = Ks[tx*4+j][k];
            #pragma unroll
            for (int i = 0; i < 4; i++)
                #pragma unroll
                for (int j = 0; j < 4; j++)
                    sc[i][j] = fmaf(rq[i], rk[j], sc[i][j]);
        }

        #pragma unroll
        for (int i = 0; i < 4; i++) {
            const int srow = q0 + ty*4 + i;
            #pragma unroll
            for (int j = 0; j < 4; j++) {
                const int t = t0 + tx*4 + j;
                float v = sc[i][j] * 0.03125f;
                bool masked = (t > srow) || (t >= S_ - padb) || (padb == 0);
                sc[i][j] = masked ? (v - 1e9f) : v;
            }
        }

        #pragma unroll
        for (int i = 0; i < 4; i++) {
            float tm = sc[i][0];
            #pragma unroll
            for (int j = 1; j < 4; j++) tm = fmaxf(tm, sc[i][j]);
            #pragma unroll
            for (int o = 8; o > 0; o >>= 1)
                tm = fmaxf(tm, __shfl_xor_sync(0xffffffffu, tm, o, 16));
            const float mnew  = fmaxf(mrow[i], tm);
            const float alpha = __expf(mrow[i] - mnew);
            float rs = 0.f;
            #pragma unroll
            for (int j = 0; j < 4; j++) {
                float p = __expf(sc[i][j] - mnew);
                sc[i][j] = p;
                rs += p;
            }
            #pragma unroll
            for (int o = 8; o > 0; o >>= 1)
                rs += __shfl_xor_sync(0xffffffffu, rs, o, 16);
            lrow[i] = lrow[i] * alpha + rs;
            mrow[i] = mnew;
            #pragma unroll
            for (int j = 0; j < 4; j++) acc[i][j] *= alpha;
            #pragma unroll
            for (int j = 0; j < 4; j++) Ps[ty*4+i][tx*4+j] = sc[i][j];
        }
        __syncthreads();

        #pragma unroll
        for (int k = 0; k < 64; k++) {
            float rp[4], rv[4];
            #pragma unroll
            for (int i = 0; i < 4; i++) rp[i] = Ps[ty*4+i][k];
            #pragma unroll
            for (int j = 0; j < 4; j++) rv[j] = Vs[k][tx*4+j];
            #pragma unroll
            for (int i = 0; i < 4; i++)
                #pragma unroll
                for (int j = 0; j < 4; j++)
                    acc[i][j] = fmaf(rp[i], rv[j], acc[i][j]);
        }
    }

    // write bf16 hi/lo split to X[b,s,h*64+d]
    #pragma unroll
    for (int i = 0; i < 4; i++) {
        const int srow = q0 + ty*4 + i;
        const float inv = 1.f / lrow[i];
        const size_t base = ((size_t)(b * S_ + srow)) * DM_ + h * 64 + tx*4;
        uint2 hv, lv;
        float r0, r1, r2, r3;
        float v0 = acc[i][0]*inv, v1 = acc[i][1]*inv, v2 = acc[i][2]*inv, v3 = acc[i][3]*inv;
        hv.x = pack2(v0, v1, &r0, &r1);
        hv.y = pack2(v2, v3, &r2, &r3);
        lv.x = pack2lo(r0, r1);
        lv.y = pack2lo(r2, r3);
        *(uint2*)(Xhi + base) = hv;
        *(uint2*)(Xlo + base) = lv;
    }
}

// ---------------------------------------------------------------------------
extern "C" void kernel_launch(void* const* d_in, const int* in_sizes, int n_in,
                              void* d_out, int out_size)
{
    const float* Q   = (const float*)d_in[0];
    const float* K   = (const float*)d_in[1];
    const float* V   = (const float*)d_in[2];
    const int*   pad = (const int*)  d_in[3];
    const float* Wq  = (const float*)d_in[4];
    const float* bq  = (const float*)d_in[5];
    const float* Wk  = (const float*)d_in[6];
    const float* bk  = (const float*)d_in[7];
    const float* Wv  = (const float*)d_in[8];
    const float* bv  = (const float*)d_in[9];
    const float* Wo  = (const float*)d_in[10];
    const float* bo  = (const float*)d_in[11];
    float* out = (float*)d_out;

    float *qh, *kh, *vh;
    __nv_bfloat16 *ahi, *alo, *whi, *wlo;
    cudaGetSymbolAddress((void**)&qh,  g_Qh);
    cudaGetSymbolAddress((void**)&kh,  g_Kh);
    cudaGetSymbolAddress((void**)&vh,  g_Vh);
    cudaGetSymbolAddress((void**)&ahi, g_Ahi);
    cudaGetSymbolAddress((void**)&alo, g_Alo);
    cudaGetSymbolAddress((void**)&whi, g_Whi);
    cudaGetSymbolAddress((void**)&wlo, g_Wlo);

    cudaFuncSetAttribute(mma_gemm,
                         cudaFuncAttributeMaxDynamicSharedMemorySize, GSMEM);
    cudaFuncSetAttribute(attn_kernel,
                         cudaFuncAttributeMaxDynamicSharedMemorySize, ATTN_SMEM);

    const int n4 = (B_*S_*DM_) / 4;          // float4 count
    const dim3 gw(32, 32), bw(32, 8);
    const dim3 gg(8, 64);                    // N tiles x M tiles

    // Q projection
    split_wT<<<gw, bw>>>(Wq, whi, wlo, 0);
    split_act<<<n4/256, 256>>>((const float4*)Q, (uint2*)ahi, (uint2*)alo, n4);
    mma_gemm<<<gg, 256, GSMEM>>>(ahi, alo, whi, wlo, bq, qh, 0);
    // K projection
    split_wT<<<gw, bw>>>(Wk, whi, wlo, 0);
    split_act<<<n4/256, 256>>>((const float4*)K, (uint2*)ahi, (uint2*)alo, n4);
    mma_gemm<<<gg, 256, GSMEM>>>(ahi, alo, whi, wlo, bk, kh, 0);
    // V projection
    split_wT<<<gw, bw>>>(Wv, whi, wlo, 0);
    split_act<<<n4/256, 256>>>((const float4*)V, (uint2*)ahi, (uint2*)alo, n4);
    mma_gemm<<<gg, 256, GSMEM>>>(ahi, alo, whi, wlo, bv, vh, 0);

    // attention -> bf16 hi/lo directly into ahi/alo
    attn_kernel<<<dim3(16, 128), 256, ATTN_SMEM>>>(pad, ahi, alo);

    // output projection
    split_wT<<<gw, bw>>>(Wo, whi, wlo, 1);
    mma_gemm<<<gg, 256, GSMEM>>>(ahi, alo, whi, wlo, bo, out, 1);
}

// round 4
// speedup vs baseline: 2.0047x; 1.0267x over previous
#include <cuda_runtime.h>
#include <cuda_bf16.h>
#include <mma.h>
#include <math.h>
#include <stdint.h>

using namespace nvcuda;

#define S_   1024
#define DM_  1024
#define B_   8
#define H_   16
#define D_   64

// ---------------- scratch (__device__ globals; no allocation) ----------------
__device__ __nv_bfloat16 g_Qhi[B_*H_*S_*D_];  // [b,h,s,d]
__device__ __nv_bfloat16 g_Qlo[B_*H_*S_*D_];
__device__ __nv_bfloat16 g_Khi[B_*H_*S_*D_];
__device__ __nv_bfloat16 g_Klo[B_*H_*S_*D_];
__device__ __nv_bfloat16 g_Vhi[B_*H_*S_*D_];
__device__ __nv_bfloat16 g_Vlo[B_*H_*S_*D_];
__device__ __nv_bfloat16 g_Ahi[B_*S_*DM_];    // activation hi/lo (inputs, then X)
__device__ __nv_bfloat16 g_Alo[B_*S_*DM_];
__device__ __nv_bfloat16 g_Whi[DM_*DM_];      // weight-transposed hi/lo [N][K]
__device__ __nv_bfloat16 g_Wlo[DM_*DM_];

// ---------------- helpers ----------------
__device__ __forceinline__ uint32_t smem_u32(const void* p) {
    uint32_t a;
    asm("{ .reg .u64 t; cvta.to.shared.u64 t, %1; cvt.u32.u64 %0, t; }"
        : "=r"(a) : "l"(p));
    return a;
}
__device__ __forceinline__ void cp16(uint32_t dst, const void* src) {
    asm volatile("cp.async.cg.shared.global [%0], [%1], 16;" :: "r"(dst), "l"(src));
}
__device__ __forceinline__ uint32_t pack2(float a, float b, float* ra, float* rb) {
    __nv_bfloat16 ha = __float2bfloat16(a), hb = __float2bfloat16(b);
    *ra = a - __bfloat162float(ha);
    *rb = b - __bfloat162float(hb);
    return (uint32_t)__bfloat16_as_ushort(ha) |
           ((uint32_t)__bfloat16_as_ushort(hb) << 16);
}
__device__ __forceinline__ uint32_t pack2lo(float a, float b) {
    __nv_bfloat16 ha = __float2bfloat16(a), hb = __float2bfloat16(b);
    return (uint32_t)__bfloat16_as_ushort(ha) |
           ((uint32_t)__bfloat16_as_ushort(hb) << 16);
}

// ---------------- conversion kernels ----------------
__global__ __launch_bounds__(256) void split_act(
    const float4* __restrict__ src, uint2* __restrict__ hi, uint2* __restrict__ lo, int n4)
{
    int i = blockIdx.x * 256 + threadIdx.x;
    if (i >= n4) return;
    float4 v = src[i];
    float rx, ry, rz, rw;
    uint2 h, l;
    h.x = pack2(v.x, v.y, &rx, &ry);
    h.y = pack2(v.z, v.w, &rz, &rw);
    l.x = pack2lo(rx, ry);
    l.y = pack2lo(rz, rw);
    hi[i] = h; lo[i] = l;
}

// weight transpose+split: out[n][k]; mode0 src=W[h][k][d] (n=h*64+d), mode1 src=Wo[k][n]
__global__ __launch_bounds__(256) void split_wT(
    const float* __restrict__ W, __nv_bfloat16* __restrict__ hi,
    __nv_bfloat16* __restrict__ lo, int mode)
{
    __shared__ float t[32][33];
    int k0 = blockIdx.x * 32, n0 = blockIdx.y * 32;
    int tx = threadIdx.x, ty = threadIdx.y;   // 32 x 8
    #pragma unroll
    for (int i = 0; i < 4; i++) {
        int k = k0 + ty + 8*i, n = n0 + tx;
        float v = mode ? W[(size_t)k * 1024 + n]
                       : W[(((size_t)(n >> 6)) * 1024 + k) * 64 + (n & 63)];
        t[ty + 8*i][tx] = v;
    }
    __syncthreads();
    #pragma unroll
    for (int i = 0; i < 4; i++) {
        int n = n0 + ty + 8*i, k = k0 + tx;
        float v = t[tx][ty + 8*i];
        __nv_bfloat16 h = __float2bfloat16(v);
        __nv_bfloat16 l = __float2bfloat16(v - __bfloat162float(h));
        hi[(size_t)n * 1024 + k] = h;
        lo[(size_t)n * 1024 + k] = l;
    }
}

// ---------------- wmma GEMM (bf16x3 emulated fp32) ----------------
#define LDSM   40
#define MATB   (128 * LDSM * 2)
#define STAGEB (4 * MATB)
#define GSMEM  (2 * STAGEB + 16 * 128 * 4)
#define EPLD   132

typedef wmma::fragment<wmma::matrix_a, 16,16,16, __nv_bfloat16, wmma::row_major> FragA;
typedef wmma::fragment<wmma::matrix_b, 16,16,16, __nv_bfloat16, wmma::col_major> FragBc;
typedef wmma::fragment<wmma::matrix_b, 16,16,16, __nv_bfloat16, wmma::row_major> FragBr;
typedef wmma::fragment<wmma::accumulator, 16,16,16, float> FragC;

__device__ __forceinline__ void issue_stage(
    const __nv_bfloat16* __restrict__ Ahi, const __nv_bfloat16* __restrict__ Alo,
    const __nv_bfloat16* __restrict__ Bhi, const __nv_bfloat16* __restrict__ Blo,
    uint32_t sbase, int stage, int m0, int n0, int k0, int tid)
{
    #pragma unroll
    for (int u = 0; u < 8; u++) {
        int chunk = u * 256 + tid;
        int mat = chunk >> 9;
        int r   = (chunk >> 2) & 127;
        int c   = chunk & 3;
        const __nv_bfloat16* g;
        if      (mat == 0) g = Ahi + (size_t)(m0 + r) * 1024 + k0 + c * 8;
        else if (mat == 1) g = Alo + (size_t)(m0 + r) * 1024 + k0 + c * 8;
        else if (mat == 2) g = Bhi + (size_t)(n0 + r) * 1024 + k0 + c * 8;
        else               g = Blo + (size_t)(n0 + r) * 1024 + k0 + c * 8;
        uint32_t dst = sbase + (uint32_t)(stage * STAGEB + mat * MATB + r * (LDSM*2) + c * 16);
        cp16(dst, g);
    }
    asm volatile("cp.async.commit_group;" ::: "memory");
}

__global__ __launch_bounds__(256) void mma_gemm(
    const __nv_bfloat16* __restrict__ Ahi, const __nv_bfloat16* __restrict__ Alo,
    const __nv_bfloat16* __restrict__ Bhi, const __nv_bfloat16* __restrict__ Blo,
    const float* __restrict__ bias, float* __restrict__ outF,
    __nv_bfloat16* __restrict__ outHi, __nv_bfloat16* __restrict__ outLo, int mode)
{
    extern __shared__ char sm[];
    float* sBias = (float*)(sm + 2 * STAGEB);
    const uint32_t sbase = smem_u32(sm);
    const int tid = threadIdx.x;
    const int wid = tid >> 5;
    const int m0 = blockIdx.y * 128;
    const int n0 = blockIdx.x * 128;
    const int wm = wid >> 2;
    const int wn = wid & 3;

    for (int idx = tid; idx < 16 * 128; idx += 256)
        sBias[idx] = bias[n0 + (idx & 127)];
    __syncthreads();

    FragC acc[4][2];
    #pragma unroll
    for (int i = 0; i < 4; i++)
        #pragma unroll
        for (int j = 0; j < 2; j++)
            wmma::load_matrix_sync(acc[i][j], sBias + wn*32 + j*16, 128, wmma::mem_row_major);

    issue_stage(Ahi, Alo, Bhi, Blo, sbase, 0, m0, n0, 0, tid);

    for (int kc = 0; kc < 32; kc++) {
        const int s = kc & 1;
        if (kc + 1 < 32) {
            issue_stage(Ahi, Alo, Bhi, Blo, sbase, s ^ 1, m0, n0, (kc + 1) * 32, tid);
            asm volatile("cp.async.wait_group 1;" ::: "memory");
        } else {
            asm volatile("cp.async.wait_group 0;" ::: "memory");
        }
        __syncthreads();

        const __nv_bfloat16* stg = (const __nv_bfloat16*)(sm + s * STAGEB);
        const __nv_bfloat16* sAh = stg;
        const __nv_bfloat16* sAl = stg + 128 * LDSM;
        const __nv_bfloat16* sBh = stg + 2 * 128 * LDSM;
        const __nv_bfloat16* sBl = stg + 3 * 128 * LDSM;

        #pragma unroll
        for (int ks = 0; ks < 2; ks++) {
            FragA ah[4], al[4];
            FragBc bh[2], bl[2];
            #pragma unroll
            for (int i = 0; i < 4; i++) {
                wmma::load_matrix_sync(ah[i], sAh + (wm*64 + i*16) * LDSM + ks*16, LDSM);
                wmma::load_matrix_sync(al[i], sAl + (wm*64 + i*16) * LDSM + ks*16, LDSM);
            }
            #pragma unroll
            for (int j = 0; j < 2; j++) {
                wmma::load_matrix_sync(bh[j], sBh + (wn*32 + j*16) * LDSM + ks*16, LDSM);
                wmma::load_matrix_sync(bl[j], sBl + (wn*32 + j*16) * LDSM + ks*16, LDSM);
            }
            #pragma unroll
            for (int i = 0; i < 4; i++)
                #pragma unroll
                for (int j = 0; j < 2; j++) {
                    wmma::mma_sync(acc[i][j], ah[i], bh[j], acc[i][j]);
                    wmma::mma_sync(acc[i][j], ah[i], bl[j], acc[i][j]);
                    wmma::mma_sync(acc[i][j], al[i], bh[j], acc[i][j]);
                }
        }
        __syncthreads();
    }

    if (mode == 1) {
        // direct fp32 store
        #pragma unroll
        for (int i = 0; i < 4; i++) {
            const int m = m0 + wm*64 + i*16;
            #pragma unroll
            for (int j = 0; j < 2; j++) {
                const int n = n0 + wn*32 + j*16;
                wmma::store_matrix_sync(outF + (size_t)m * 1024 + n, acc[i][j],
                                        1024, wmma::mem_row_major);
            }
        }
        return;
    }

    // mode 0: smem roundtrip, split to bf16 hi/lo at [b,h,s,d]
    float* sEpi = (float*)sm;
    #pragma unroll
    for (int i = 0; i < 4; i++)
        #pragma unroll
        for (int j = 0; j < 2; j++)
            wmma::store_matrix_sync(sEpi + (wm*64 + i*16) * EPLD + wn*32 + j*16,
                                    acc[i][j], EPLD, wmma::mem_row_major);
    __syncthreads();

    #pragma unroll
    for (int u = 0; u < 32; u++) {
        int e2 = u * 256 + tid;          // pair index (2 elems), 8192 pairs
        int r = e2 >> 6;                 // 0..127
        int c = (e2 & 63) * 2;           // 0..126 even
        float v0 = sEpi[r * EPLD + c];
        float v1 = sEpi[r * EPLD + c + 1];
        float r0, r1;
        uint32_t hv = pack2(v0, v1, &r0, &r1);
        uint32_t lv = pack2lo(r0, r1);
        const int m = m0 + r, n = n0 + c;
        const int b = m >> 10, srow = m & 1023;
        const int h = n >> 6,  d = n & 63;
        size_t addr = ((((size_t)(b*16 + h)) * 1024 + srow) * 64 + d);
        *(uint32_t*)(outHi + addr) = hv;
        *(uint32_t*)(outLo + addr) = lv;
    }
}

// ---------------- tensor-core flash attention (bf16x3, exact ref mask) -------
#define ALD 72        // bf16 tile leading dim (elements)
#define SLD 68        // fp32 tile leading dim (elements)
#define oQh 0
#define oQl (oQh + 64*ALD*2)
#define oKh (oQl + 64*ALD*2)
#define oKl (oKh + 64*ALD*2)
#define oVh (oKl + 64*ALD*2)
#define oVl (oVh + 64*ALD*2)
#define oPh (oVl + 64*ALD*2)
#define oPl (oPh + 64*ALD*2)
#define oSS (oPl + 64*ALD*2)
#define oOO (oSS + 64*SLD*4)
#define oRM (oOO + 64*SLD*4)
#define oRL (oRM + 256)
#define oAL (oRL + 256)
#define ATTN_SMEM (oAL + 256)

__device__ __forceinline__ void ld_tile64(
    const __nv_bfloat16* __restrict__ g, __nv_bfloat16* __restrict__ s, int tid)
{
    // 64x64 bf16 tile, global rows contiguous (8KB block), smem rows padded to ALD
    #pragma unroll
    for (int u = 0; u < 4; u++) {
        int chunk = u * 128 + tid;       // 512 chunks of 16B
        int r = chunk >> 3, c = chunk & 7;
        uint4 v = *(const uint4*)(g + (size_t)r * 64 + c * 8);
        *(uint4*)(s + r * ALD + c * 8) = v;
    }
}

__global__ __launch_bounds__(128) void attn_mma(
    const int* __restrict__ pad,
    __nv_bfloat16* __restrict__ Xhi, __nv_bfloat16* __restrict__ Xlo)
{
    extern __shared__ char sm[];
    __nv_bfloat16* sQh = (__nv_bfloat16*)(sm + oQh);
    __nv_bfloat16* sQl = (__nv_bfloat16*)(sm + oQl);
    __nv_bfloat16* sKh = (__nv_bfloat16*)(sm + oKh);
    __nv_bfloat16* sKl = (__nv_bfloat16*)(sm + oKl);
    __nv_bfloat16* sVh = (__nv_bfloat16*)(sm + oVh);
    __nv_bfloat16* sVl = (__nv_bfloat16*)(sm + oVl);
    __nv_bfloat16* sPh = (__nv_bfloat16*)(sm + oPh);
    __nv_bfloat16* sPl = (__nv_bfloat16*)(sm + oPl);
    float* sS = (float*)(sm + oSS);
    float* sO = (float*)(sm + oOO);
    float* rm = (float*)(sm + oRM);
    float* rl = (float*)(sm + oRL);
    float* sal = (float*)(sm + oAL);

    const int qt = blockIdx.x;
    const int bh = blockIdx.y;
    const int b  = bh >> 4;
    const int h  = bh & 15;
    const int padb = pad[b];
    const int tid = threadIdx.x;
    const int w = tid >> 5;
    const int q0 = qt * 64;
    const int tlim = S_ - padb;

    const size_t hoff = (size_t)bh * S_ * D_;

    // load Q tile hi/lo
    ld_tile64(g_Qhi + hoff + (size_t)q0 * 64, sQh, tid);
    ld_tile64(g_Qlo + hoff + (size_t)q0 * 64, sQl, tid);
    // init O, m, l
    for (int i = tid; i < 64 * SLD; i += 128) sO[i] = 0.f;
    if (tid < 64) { rm[tid] = -INFINITY; rl[tid] = 0.f; }
    __syncthreads();

    FragA qh[4], ql[4];
    #pragma unroll
    for (int ks = 0; ks < 4; ks++) {
        wmma::load_matrix_sync(qh[ks], sQh + (w*16) * ALD + ks*16, ALD);
        wmma::load_matrix_sync(ql[ks], sQl + (w*16) * ALD + ks*16, ALD);
    }

    const int r = tid >> 1;          // softmax row (within warp's block)
    const int half = tid & 1;
    const int srow = q0 + r;

    for (int jt = 0; jt < 16; jt++) {
        const int t0 = jt * 64;
        if (padb != 0 && (t0 > q0 + 63 || t0 >= tlim)) continue;

        __syncthreads();
        ld_tile64(g_Khi + hoff + (size_t)t0 * 64, sKh, tid);
        ld_tile64(g_Klo + hoff + (size_t)t0 * 64, sKl, tid);
        ld_tile64(g_Vhi + hoff + (size_t)t0 * 64, sVh, tid);
        ld_tile64(g_Vlo + hoff + (size_t)t0 * 64, sVl, tid);
        __syncthreads();

        // ---- S = Q K^T (bf16x3) ----
        {
            FragC acc[4];
            #pragma unroll
            for (int j = 0; j < 4; j++) wmma::fill_fragment(acc[j], 0.f);
            #pragma unroll
            for (int j = 0; j < 4; j++) {
                #pragma unroll
                for (int ks = 0; ks < 4; ks++) {
                    FragBc kh, kl;
                    wmma::load_matrix_sync(kh, sKh + (j*16) * ALD + ks*16, ALD);
                    wmma::load_matrix_sync(kl, sKl + (j*16) * ALD + ks*16, ALD);
                    wmma::mma_sync(acc[j], qh[ks], kh, acc[j]);
                    wmma::mma_sync(acc[j], qh[ks], kl, acc[j]);
                    wmma::mma_sync(acc[j], ql[ks], kh, acc[j]);
                }
            }
            #pragma unroll
            for (int j = 0; j < 4; j++)
                wmma::store_matrix_sync(sS + (w*16) * SLD + j*16, acc[j],
                                        SLD, wmma::mem_row_major);
        }
        __syncwarp();

        // ---- softmax (2 threads per row, 32 cols each) ----
        {
            const float* Srow = sS + r * SLD + half * 32;
            const int tbase = t0 + half * 32;
            float mloc = -INFINITY;
            #pragma unroll
            for (int c = 0; c < 32; c++) {
                const int t = tbase + c;
                float v = Srow[c] * 0.03125f;
                if ((t > srow) | (t >= tlim) | (padb == 0)) v -= 1e9f;
                mloc = fmaxf(mloc, v);
            }
            mloc = fmaxf(mloc, __shfl_xor_sync(0xffffffffu, mloc, 1));
            const float mold = rm[r];
            const float mnew = fmaxf(mold, mloc);
            const float alpha = __expf(mold - mnew);
            float lsum = 0.f;
            __nv_bfloat16* Pr = sPh + r * ALD + half * 32;
            __nv_bfloat16* Pl = sPl + r * ALD + half * 32;
            #pragma unroll
            for (int c = 0; c < 32; c++) {
                const int t = tbase + c;
                float v = Srow[c] * 0.03125f;
                if ((t > srow) | (t >= tlim) | (padb == 0)) v -= 1e9f;
                float p = __expf(v - mnew);
                lsum += p;
                __nv_bfloat16 ph = __float2bfloat16(p);
                Pr[c] = ph;
                Pl[c] = __float2bfloat16(p - __bfloat162float(ph));
            }
            lsum += __shfl_xor_sync(0xffffffffu, lsum, 1);
            if (half == 0) {
                rm[r] = mnew;
                rl[r] = rl[r] * alpha + lsum;
                sal[r] = alpha;
            }
        }
        __syncwarp();

        // ---- PV (bf16x3) ----
        {
            FragA ph[4], pl[4];
            #pragma unroll
            for (int ks = 0; ks < 4; ks++) {
                wmma::load_matrix_sync(ph[ks], sPh + (w*16) * ALD + ks*16, ALD);
                wmma::load_matrix_sync(pl[ks], sPl + (w*16) * ALD + ks*16, ALD);
            }
            FragC oacc[4];
            #pragma unroll
            for (int n = 0; n < 4; n++) wmma::fill_fragment(oacc[n], 0.f);
            #pragma unroll
            for (int n = 0; n < 4; n++) {
                #pragma unroll
                for (int ks = 0; ks < 4; ks++) {
                    FragBr vh, vl;
                    wmma::load_matrix_sync(vh, sVh + (ks*16) * ALD + n*16, ALD);
                    wmma::load_matrix_sync(vl, sVl + (ks*16) * ALD + n*16, ALD);
                    wmma::mma_sync(oacc[n], ph[ks], vh, oacc[n]);
                    wmma::mma_sync(oacc[n], ph[ks], vl, oacc[n]);
                    wmma::mma_sync(oacc[n], pl[ks], vh, oacc[n]);
                }
            }
            #pragma unroll
            for (int n = 0; n < 4; n++)
                wmma::store_matrix_sync(sS + (w*16) * SLD + n*16, oacc[n],
                                        SLD, wmma::mem_row_major);
        }
        __syncwarp();

        // ---- O = O*alpha + PV ----
        {
            const float a = sal[r];
            float* Or = sO + r * SLD + half * 32;
            const float* Pv = sS + r * SLD + half * 32;
            #pragma unroll
            for (int c = 0; c < 32; c++)
                Or[c] = Or[c] * a + Pv[c];
        }
    }

    __syncwarp();
    // epilogue: normalize, split, store
    {
        const float inv = 1.f / rl[r];
        const float* Or = sO + r * SLD + half * 32;
        const size_t base = ((size_t)(b * S_ + q0 + r)) * DM_ + h * 64 + half * 32;
        #pragma unroll
        for (int c = 0; c < 32; c += 2) {
            float v0 = Or[c] * inv, v1 = Or[c+1] * inv;
            float r0, r1;
            uint32_t hv = pack2(v0, v1, &r0, &r1);
            uint32_t lv = pack2lo(r0, r1);
            *(uint32_t*)(Xhi + base + c) = hv;
            *(uint32_t*)(Xlo + base + c) = lv;
        }
    }
}

// ---------------------------------------------------------------------------
extern "C" void kernel_launch(void* const* d_in, const int* in_sizes, int n_in,
                              void* d_out, int out_size)
{
    const float* Q   = (const float*)d_in[0];
    const float* K   = (const float*)d_in[1];
    const float* V   = (const float*)d_in[2];
    const int*   pad = (const int*)  d_in[3];
    const float* Wq  = (const float*)d_in[4];
    const float* bq  = (const float*)d_in[5];
    const float* Wk  = (const float*)d_in[6];
    const float* bk  = (const float*)d_in[7];
    const float* Wv  = (const float*)d_in[8];
    const float* bv  = (const float*)d_in[9];
    const float* Wo  = (const float*)d_in[10];
    const float* bo  = (const float*)d_in[11];
    float* out = (float*)d_out;

    __nv_bfloat16 *qhi, *qlo, *khi, *klo, *vhi, *vlo, *ahi, *alo, *whi, *wlo;
    cudaGetSymbolAddress((void**)&qhi, g_Qhi);
    cudaGetSymbolAddress((void**)&qlo, g_Qlo);
    cudaGetSymbolAddress((void**)&khi, g_Khi);
    cudaGetSymbolAddress((void**)&klo, g_Klo);
    cudaGetSymbolAddress((void**)&vhi, g_Vhi);
    cudaGetSymbolAddress((void**)&vlo, g_Vlo);
    cudaGetSymbolAddress((void**)&ahi, g_Ahi);
    cudaGetSymbolAddress((void**)&alo, g_Alo);
    cudaGetSymbolAddress((void**)&whi, g_Whi);
    cudaGetSymbolAddress((void**)&wlo, g_Wlo);

    cudaFuncSetAttribute(mma_gemm,
                         cudaFuncAttributeMaxDynamicSharedMemorySize, GSMEM);
    cudaFuncSetAttribute(attn_mma,
                         cudaFuncAttributeMaxDynamicSharedMemorySize, ATTN_SMEM);

    const int n4 = (B_*S_*DM_) / 4;
    const dim3 gw(32, 32), bw(32, 8);
    const dim3 gg(8, 64);

    // Q projection
    split_wT<<<gw, bw>>>(Wq, whi, wlo, 0);
    split_act<<<n4/256, 256>>>((const float4*)Q, (uint2*)ahi, (uint2*)alo, n4);
    mma_gemm<<<gg, 256, GSMEM>>>(ahi, alo, whi, wlo, bq, nullptr, qhi, qlo, 0);
    // K projection
    split_wT<<<gw, bw>>>(Wk, whi, wlo, 0);
    split_act<<<n4/256, 256>>>((const float4*)K, (uint2*)ahi, (uint2*)alo, n4);
    mma_gemm<<<gg, 256, GSMEM>>>(ahi, alo, whi, wlo, bk, nullptr, khi, klo, 0);
    // V projection
    split_wT<<<gw, bw>>>(Wv, whi, wlo, 0);
    split_act<<<n4/256, 256>>>((const float4*)V, (uint2*)ahi, (uint2*)alo, n4);
    mma_gemm<<<gg, 256, GSMEM>>>(ahi, alo, whi, wlo, bv, nullptr, vhi, vlo, 0);

    // attention -> X hi/lo into ahi/alo
    attn_mma<<<dim3(16, 128), 128, ATTN_SMEM>>>(pad, ahi, alo);

    // output projection (fp32 out)
    split_wT<<<gw, bw>>>(Wo, whi, wlo, 1);
    mma_gemm<<<gg, 256, GSMEM>>>(ahi, alo, whi, wlo, bo, out, nullptr, nullptr, 1);
}